// round 1
// baseline (speedup 1.0000x reference)
#include <cuda_runtime.h>

#define NGRAPH 1024
#define NPG    128
#define HID    64
#define EPG    2048            // edges per graph (NPG*16)
#define GT     512             // threads in GNN kernel
#define NW     (GT/32)         // 16 warps

// ---- global scratch (no allocations allowed) ----
__device__ float g_h [(size_t)NGRAPH * NPG * HID];   // final node features [N,64]
__device__ float g_h1[NGRAPH * 128];                 // head hidden [1024,128]

// ---- shared memory layout for the per-graph GNN CTA ----
struct SM {
    float H[NPG * HID];      // current node features
    float A[NPG * HID];      // xl / xw
    float B[NPG * HID];      // xr (GATv2 only)
    float W[HID * HID];      // weight tile (or Wl|Wr packed)
    float e[EPG];            // edge logits -> normalized attention
    float xin[NPG * 4];      // raw input features
    float vec0[HID], vec1[HID], vec2[HID], vec3[HID];
    float lng[HID], lnb[HID];
    float alS[NPG], alD[NPG];
    int   scanw[4];
    int   off[NPG + 1];
    int   cnt[NPG];
    unsigned short order[EPG];   // edge ids sorted by dst (CSR)
    unsigned char  ls[EPG], ld[EPG];
};

__device__ __forceinline__ float lrelu(float x, float s) { return x >= 0.f ? x : s * x; }

__device__ __forceinline__ float wsum(float v) {
#pragma unroll
    for (int o = 16; o; o >>= 1) v += __shfl_xor_sync(0xffffffffu, v, o);
    return v;
}
__device__ __forceinline__ float wmax(float v) {
#pragma unroll
    for (int o = 16; o; o >>= 1) v = fmaxf(v, __shfl_xor_sync(0xffffffffu, v, o));
    return v;
}

// ---- one GATConv layer (with self-loops), fully in SMEM ----
__device__ void gat_layer(SM* sm, const float* __restrict__ Wg,
                          const float* __restrict__ as_, const float* __restrict__ ad_,
                          const float* __restrict__ bias,
                          int tid, int wid, int lane)
{
    for (int i = tid; i < HID * HID; i += GT) sm->W[i] = Wg[i];
    if (tid < HID) { sm->vec0[tid] = as_[tid]; sm->vec1[tid] = ad_[tid]; sm->vec2[tid] = bias[tid]; }
    __syncthreads();

    // xw = H @ W -> A   (thread computes 4 rows x 4 cols)
    {
        int rg = tid >> 4, cg = tid & 15;
        int v0 = rg * 4, k0 = cg * 4;
        float acc[4][4];
#pragma unroll
        for (int r = 0; r < 4; r++)
#pragma unroll
            for (int c = 0; c < 4; c++) acc[r][c] = 0.f;
        for (int i = 0; i < HID; i++) {
            float4 wv = *(const float4*)&sm->W[i * HID + k0];
#pragma unroll
            for (int r = 0; r < 4; r++) {
                float hv = sm->H[(v0 + r) * HID + i];
                acc[r][0] = fmaf(hv, wv.x, acc[r][0]);
                acc[r][1] = fmaf(hv, wv.y, acc[r][1]);
                acc[r][2] = fmaf(hv, wv.z, acc[r][2]);
                acc[r][3] = fmaf(hv, wv.w, acc[r][3]);
            }
        }
#pragma unroll
        for (int r = 0; r < 4; r++) {
            float4 o = make_float4(acc[r][0], acc[r][1], acc[r][2], acc[r][3]);
            *(float4*)&sm->A[(v0 + r) * HID + k0] = o;
        }
    }
    __syncthreads();

    // per-node attention scalars al_s, al_d
    for (int v = wid; v < NPG; v += NW) {
        float x0 = sm->A[v * HID + lane], x1 = sm->A[v * HID + lane + 32];
        float ps = x0 * sm->vec0[lane] + x1 * sm->vec0[lane + 32];
        float pd = x0 * sm->vec1[lane] + x1 * sm->vec1[lane + 32];
        ps = wsum(ps); pd = wsum(pd);
        if (lane == 0) { sm->alS[v] = ps; sm->alD[v] = pd; }
    }
    __syncthreads();

    // edge logits
    for (int i = tid; i < EPG; i += GT)
        sm->e[i] = lrelu(sm->alS[sm->ls[i]] + sm->alD[sm->ld[i]], 0.2f);
    __syncthreads();

    // segment softmax over {in-edges(v)} U {self-loop}
    for (int v = wid; v < NPG; v += NW) {
        int o0 = sm->off[v], o1 = sm->off[v + 1];
        float m = -3.4e38f;
        for (int j = o0 + lane; j < o1; j += 32) m = fmaxf(m, sm->e[sm->order[j]]);
        m = wmax(m);
        float lp = lrelu(sm->alS[v] + sm->alD[v], 0.2f);
        m = fmaxf(m, lp);
        float ps = 0.f;
        for (int j = o0 + lane; j < o1; j += 32) {
            float ex = expf(sm->e[sm->order[j]] - m);
            sm->e[sm->order[j]] = ex;
            ps += ex;
        }
        ps = wsum(ps);
        float exl = expf(lp - m);
        float inv = 1.f / (ps + exl + 1e-16f);
        for (int j = o0 + lane; j < o1; j += 32) sm->e[sm->order[j]] *= inv;
        if (lane == 0) sm->alS[v] = exl * inv;   // self-loop coefficient
    }
    __syncthreads();

    // aggregate -> B
    for (int v = wid; v < NPG; v += NW) {
        float a0 = 0.f, a1 = 0.f;
        int o0 = sm->off[v], o1 = sm->off[v + 1];
        for (int j = o0; j < o1; j++) {
            int eid = sm->order[j];
            float a = sm->e[eid];
            int s = sm->ls[eid];
            a0 = fmaf(a, sm->A[s * HID + lane], a0);
            a1 = fmaf(a, sm->A[s * HID + lane + 32], a1);
        }
        float al = sm->alS[v];
        a0 = fmaf(al, sm->A[v * HID + lane], a0);
        a1 = fmaf(al, sm->A[v * HID + lane + 32], a1);
        sm->B[v * HID + lane] = a0;
        sm->B[v * HID + lane + 32] = a1;
    }
    __syncthreads();

    // H = relu(B + bias)
    for (int i = tid; i < NPG * HID; i += GT)
        sm->H[i] = fmaxf(sm->B[i] + sm->vec2[i & (HID - 1)], 0.f);
    __syncthreads();
}

// ---- kernel 1: full 3-layer GNN, one CTA per graph ----
__global__ void __launch_bounds__(GT, 1) gnn_kernel(
    const float* __restrict__ x, const int* __restrict__ ei,
    const float* __restrict__ Wl, const float* __restrict__ bl,
    const float* __restrict__ Wr, const float* __restrict__ br,
    const float* __restrict__ attv, const float* __restrict__ bv2,
    const float* __restrict__ Wg1, const float* __restrict__ as1,
    const float* __restrict__ ad1, const float* __restrict__ bg1,
    const float* __restrict__ Wg2, const float* __restrict__ as2,
    const float* __restrict__ ad2, const float* __restrict__ bg2,
    const float* __restrict__ lngp, const float* __restrict__ lnbp)
{
    extern __shared__ char smraw[];
    SM* sm = (SM*)smraw;
    int tid = threadIdx.x, lane = tid & 31, wid = tid >> 5;
    int g = blockIdx.x, base = g * NPG;
    const int* srcp = ei;
    const int* dstp = ei + (size_t)NGRAPH * EPG;

    // ---- load per-graph inputs ----
    for (int i = tid; i < NPG * 4; i += GT) sm->xin[i] = x[(size_t)base * 4 + i];
    for (int i = tid; i < EPG; i += GT) {
        sm->ls[i] = (unsigned char)(srcp[(size_t)g * EPG + i] - base);
        sm->ld[i] = (unsigned char)(dstp[(size_t)g * EPG + i] - base);
    }
    if (tid < HID) { sm->lng[tid] = lngp[tid]; sm->lnb[tid] = lnbp[tid]; }
    for (int i = tid; i < NPG; i += GT) sm->cnt[i] = 0;
    __syncthreads();

    // ---- build CSR by dst (counting sort), reused by all 3 layers ----
    for (int i = tid; i < EPG; i += GT) atomicAdd(&sm->cnt[sm->ld[i]], 1);
    __syncthreads();
    int myv = 0, sc = 0;
    if (tid < NPG) {
        myv = sm->cnt[tid]; sc = myv;
#pragma unroll
        for (int o = 1; o < 32; o <<= 1) {
            int n = __shfl_up_sync(0xffffffffu, sc, o);
            if (lane >= o) sc += n;
        }
        if (lane == 31) sm->scanw[wid] = sc;
    }
    __syncthreads();
    if (tid < NPG) {
        int add = 0;
        for (int i = 0; i < wid; i++) add += sm->scanw[i];
        sm->off[tid] = add + sc - myv;
    }
    if (tid == 0) sm->off[NPG] = EPG;
    __syncthreads();
    if (tid < NPG) sm->cnt[tid] = sm->off[tid];
    __syncthreads();
    for (int i = tid; i < EPG; i += GT) {
        int pos = atomicAdd(&sm->cnt[sm->ld[i]], 1);
        sm->order[pos] = (unsigned short)i;
    }

    // ---- GATv2 layer ----
    for (int i = tid; i < 4 * HID; i += GT) { sm->W[i] = Wl[i]; sm->W[4 * HID + i] = Wr[i]; }
    if (tid < HID) { sm->vec0[tid] = bl[tid]; sm->vec1[tid] = br[tid];
                     sm->vec2[tid] = attv[tid]; sm->vec3[tid] = bv2[tid]; }
    __syncthreads();
    {   // xl -> A, xr -> B   (IN = 4 so this is tiny)
        int k = tid & (HID - 1), vg = tid >> 6;   // vg 0..7
        for (int r = 0; r < 16; r++) {
            int v = vg * 16 + r;
            float a = sm->vec0[k], b = sm->vec1[k];
#pragma unroll
            for (int i = 0; i < 4; i++) {
                float xv = sm->xin[v * 4 + i];
                a = fmaf(xv, sm->W[i * HID + k], a);
                b = fmaf(xv, sm->W[4 * HID + i * HID + k], b);
            }
            sm->A[v * HID + k] = a;
            sm->B[v * HID + k] = b;
        }
    }
    __syncthreads();
    // edge logits: e = lrelu(xl[s] + xr[d], 0.2) . att   (warp per edge)
    for (int e2 = wid; e2 < EPG; e2 += NW) {
        int s = sm->ls[e2], d = sm->ld[e2];
        float t0 = lrelu(sm->A[s * HID + lane] + sm->B[d * HID + lane], 0.2f) * sm->vec2[lane];
        float t1 = lrelu(sm->A[s * HID + lane + 32] + sm->B[d * HID + lane + 32], 0.2f) * sm->vec2[lane + 32];
        float sv = wsum(t0 + t1);
        if (lane == 0) sm->e[e2] = sv;
    }
    __syncthreads();
    // softmax (no self-loop in GATv2)
    for (int v = wid; v < NPG; v += NW) {
        int o0 = sm->off[v], o1 = sm->off[v + 1];
        float m = -3.4e38f;
        for (int j = o0 + lane; j < o1; j += 32) m = fmaxf(m, sm->e[sm->order[j]]);
        m = wmax(m);
        float ps = 0.f;
        for (int j = o0 + lane; j < o1; j += 32) {
            float ex = expf(sm->e[sm->order[j]] - m);
            sm->e[sm->order[j]] = ex;
            ps += ex;
        }
        ps = wsum(ps);
        float inv = 1.f / (ps + 1e-16f);
        for (int j = o0 + lane; j < o1; j += 32) sm->e[sm->order[j]] *= inv;
    }
    __syncthreads();
    // aggregate + bias + lrelu(0.01) + layernorm, fused -> H
    for (int v = wid; v < NPG; v += NW) {
        float a0 = 0.f, a1 = 0.f;
        int o0 = sm->off[v], o1 = sm->off[v + 1];
        for (int j = o0; j < o1; j++) {
            int eid = sm->order[j];
            float a = sm->e[eid];
            int s = sm->ls[eid];
            a0 = fmaf(a, sm->A[s * HID + lane], a0);
            a1 = fmaf(a, sm->A[s * HID + lane + 32], a1);
        }
        float t0 = lrelu(a0 + sm->vec3[lane], 0.01f);
        float t1 = lrelu(a1 + sm->vec3[lane + 32], 0.01f);
        float mean = wsum(t0 + t1) * (1.f / 64.f);
        float d0 = t0 - mean, d1 = t1 - mean;
        float var = wsum(d0 * d0 + d1 * d1) * (1.f / 64.f);
        float rstd = rsqrtf(var + 1e-5f);
        sm->H[v * HID + lane]      = d0 * rstd * sm->lng[lane] + sm->lnb[lane];
        sm->H[v * HID + lane + 32] = d1 * rstd * sm->lng[lane + 32] + sm->lnb[lane + 32];
    }
    __syncthreads();

    // ---- GAT layers 1 & 2 ----
    gat_layer(sm, Wg1, as1, ad1, bg1, tid, wid, lane);
    gat_layer(sm, Wg2, as2, ad2, bg2, tid, wid, lane);

    // ---- write final features ----
    const float4* Hv = (const float4*)sm->H;
    float4* outp = (float4*)(g_h + (size_t)g * NPG * HID);
    for (int i = tid; i < NPG * HID / 4; i += GT) outp[i] = Hv[i];
}

// ---- kernel 2a: init h1 with bias ----
__global__ void init_h1(const float* __restrict__ b1)
{
    int i = blockIdx.x * blockDim.x + threadIdx.x;
    if (i < NGRAPH * 128) g_h1[i] = b1[i & 127];
}

// ---- kernel 2b: split-K GEMM  h1 += h[1024,8192] @ W1[8192,128] ----
__global__ void __launch_bounds__(256) head_gemm(const float* __restrict__ W1)
{
    __shared__ float As[64][16];
    __shared__ float Bs[16][128];
    int m0 = blockIdx.x * 64;
    int kbase = blockIdx.y * 512;
    int tid = threadIdx.x;
    int tx = tid & 15, ty = tid >> 4;
    int r0 = ty * 4, c0 = tx * 8;
    float acc[4][8];
#pragma unroll
    for (int r = 0; r < 4; r++)
#pragma unroll
        for (int c = 0; c < 8; c++) acc[r][c] = 0.f;

    int ar = tid >> 2, aq = (tid & 3) * 4;
    int brr = tid >> 4, bc = (tid & 15) * 8;
    for (int kk = kbase; kk < kbase + 512; kk += 16) {
        *(float4*)&As[ar][aq]     = *(const float4*)&g_h[(size_t)(m0 + ar) * 8192 + kk + aq];
        *(float4*)&Bs[brr][bc]     = *(const float4*)&W1[(size_t)(kk + brr) * 128 + bc];
        *(float4*)&Bs[brr][bc + 4] = *(const float4*)&W1[(size_t)(kk + brr) * 128 + bc + 4];
        __syncthreads();
#pragma unroll
        for (int k = 0; k < 16; k++) {
            float a0 = As[r0][k], a1 = As[r0 + 1][k], a2 = As[r0 + 2][k], a3 = As[r0 + 3][k];
            float4 bA = *(float4*)&Bs[k][c0];
            float4 bB = *(float4*)&Bs[k][c0 + 4];
            acc[0][0] = fmaf(a0, bA.x, acc[0][0]); acc[0][1] = fmaf(a0, bA.y, acc[0][1]);
            acc[0][2] = fmaf(a0, bA.z, acc[0][2]); acc[0][3] = fmaf(a0, bA.w, acc[0][3]);
            acc[0][4] = fmaf(a0, bB.x, acc[0][4]); acc[0][5] = fmaf(a0, bB.y, acc[0][5]);
            acc[0][6] = fmaf(a0, bB.z, acc[0][6]); acc[0][7] = fmaf(a0, bB.w, acc[0][7]);
            acc[1][0] = fmaf(a1, bA.x, acc[1][0]); acc[1][1] = fmaf(a1, bA.y, acc[1][1]);
            acc[1][2] = fmaf(a1, bA.z, acc[1][2]); acc[1][3] = fmaf(a1, bA.w, acc[1][3]);
            acc[1][4] = fmaf(a1, bB.x, acc[1][4]); acc[1][5] = fmaf(a1, bB.y, acc[1][5]);
            acc[1][6] = fmaf(a1, bB.z, acc[1][6]); acc[1][7] = fmaf(a1, bB.w, acc[1][7]);
            acc[2][0] = fmaf(a2, bA.x, acc[2][0]); acc[2][1] = fmaf(a2, bA.y, acc[2][1]);
            acc[2][2] = fmaf(a2, bA.z, acc[2][2]); acc[2][3] = fmaf(a2, bA.w, acc[2][3]);
            acc[2][4] = fmaf(a2, bB.x, acc[2][4]); acc[2][5] = fmaf(a2, bB.y, acc[2][5]);
            acc[2][6] = fmaf(a2, bB.z, acc[2][6]); acc[2][7] = fmaf(a2, bB.w, acc[2][7]);
            acc[3][0] = fmaf(a3, bA.x, acc[3][0]); acc[3][1] = fmaf(a3, bA.y, acc[3][1]);
            acc[3][2] = fmaf(a3, bA.z, acc[3][2]); acc[3][3] = fmaf(a3, bA.w, acc[3][3]);
            acc[3][4] = fmaf(a3, bB.x, acc[3][4]); acc[3][5] = fmaf(a3, bB.y, acc[3][5]);
            acc[3][6] = fmaf(a3, bB.z, acc[3][6]); acc[3][7] = fmaf(a3, bB.w, acc[3][7]);
        }
        __syncthreads();
    }
#pragma unroll
    for (int r = 0; r < 4; r++)
#pragma unroll
        for (int c = 0; c < 8; c++)
            atomicAdd(&g_h1[(m0 + r0 + r) * 128 + c0 + c], acc[r][c]);
}

// ---- kernel 3: out = sigmoid(lrelu(h1,0.01) @ W2 + b2), one warp per graph ----
__global__ void head_final(const float* __restrict__ W2, const float* __restrict__ b2,
                           float* __restrict__ outp)
{
    int g = blockIdx.x * 8 + (threadIdx.x >> 5);
    int lane = threadIdx.x & 31;
    float4 h = *(const float4*)&g_h1[g * 128 + lane * 4];
    h.x = lrelu(h.x, 0.01f); h.y = lrelu(h.y, 0.01f);
    h.z = lrelu(h.z, 0.01f); h.w = lrelu(h.w, 0.01f);
    float4 w = *(const float4*)&W2[lane * 4];
    float p = h.x * w.x + h.y * w.y + h.z * w.z + h.w * w.w;
    p = wsum(p);
    if (lane == 0) outp[g] = 1.f / (1.f + expf(-(p + b2[0])));
}

extern "C" void kernel_launch(void* const* d_in, const int* in_sizes, int n_in,
                              void* d_out, int out_size)
{
    const float* x    = (const float*)d_in[0];
    const int*   ei   = (const int*)  d_in[1];
    const float* Wl   = (const float*)d_in[2];
    const float* bl   = (const float*)d_in[3];
    const float* Wr   = (const float*)d_in[4];
    const float* br   = (const float*)d_in[5];
    const float* attv = (const float*)d_in[6];
    const float* bv2  = (const float*)d_in[7];
    const float* Wg1  = (const float*)d_in[8];
    const float* as1  = (const float*)d_in[9];
    const float* ad1  = (const float*)d_in[10];
    const float* bg1  = (const float*)d_in[11];
    const float* Wg2  = (const float*)d_in[12];
    const float* as2  = (const float*)d_in[13];
    const float* ad2  = (const float*)d_in[14];
    const float* bg2  = (const float*)d_in[15];
    const float* lng  = (const float*)d_in[16];
    const float* lnb  = (const float*)d_in[17];
    const float* W1   = (const float*)d_in[18];
    const float* b1   = (const float*)d_in[19];
    const float* W2   = (const float*)d_in[20];
    const float* b2   = (const float*)d_in[21];
    float* outp = (float*)d_out;

    int smem = (int)sizeof(SM);
    cudaFuncSetAttribute(gnn_kernel, cudaFuncAttributeMaxDynamicSharedMemorySize, smem);

    gnn_kernel<<<NGRAPH, GT, smem>>>(x, ei, Wl, bl, Wr, br, attv, bv2,
                                     Wg1, as1, ad1, bg1, Wg2, as2, ad2, bg2, lng, lnb);
    init_h1<<<(NGRAPH * 128 + 255) / 256, 256>>>(b1);
    head_gemm<<<dim3(16, 16), 256>>>(W1);
    head_final<<<NGRAPH / 8, 256>>>(W2, b2, outp);
}

// round 4
// speedup vs baseline: 1.3818x; 1.3818x over previous
#include <cuda_runtime.h>

#define NGRAPH 1024
#define NPG    128
#define HID    64
#define EPG    2048            // edges per graph (NPG*16)
#define GT     512             // threads in GNN kernel
#define NW     (GT/32)         // 16 warps

// ---- global scratch (no allocations allowed) ----
__device__ float g_h [(size_t)NGRAPH * NPG * HID];   // final node features [N,64]
__device__ float g_h1[NGRAPH * 128];                 // head hidden [1024,128]

// ---- shared memory layout: ~98KB -> 2 CTAs/SM ----
struct SM {
    float H[NPG * HID];        // 32KB  node features (also xr in GATv2)
    float A[NPG * HID];        // 32KB  xl / xw
    float W[HID * HID];        // 16KB  weight tile
    float e[EPG];              //  8KB  CSR-ordered logits / exp values
    unsigned char csrc[EPG];   //  2KB  CSR-ordered source node
    unsigned char cdst[EPG];   //  2KB  CSR-ordered dest node
    float xin[NPG * 4];        //  2KB
    float vec0[HID], vec1[HID], vec2[HID], vec3[HID];
    float lng[HID], lnb[HID];
    float alS[NPG], alD[NPG];
    int   off[NPG + 1];
    int   cnt[NPG];
    int   scanw[4];
};

__device__ __forceinline__ float lrelu(float x, float s) { return x >= 0.f ? x : s * x; }

__device__ __forceinline__ float wsum(float v) {
#pragma unroll
    for (int o = 16; o; o >>= 1) v += __shfl_xor_sync(0xffffffffu, v, o);
    return v;
}
__device__ __forceinline__ float wmax(float v) {
#pragma unroll
    for (int o = 16; o; o >>= 1) v = fmaxf(v, __shfl_xor_sync(0xffffffffu, v, o));
    return v;
}

// 64x64 GEMM in smem: A = H @ W. Thread = 4 rows x 4 cols, k-chunks of 4 via float4.
__device__ __forceinline__ void gemm64(SM* sm, int tid)
{
    int rg = tid >> 4, cg = tid & 15;
    int v0 = rg * 4, k0 = cg * 4;
    float acc[4][4];
#pragma unroll
    for (int r = 0; r < 4; r++)
#pragma unroll
        for (int c = 0; c < 4; c++) acc[r][c] = 0.f;
#pragma unroll 4
    for (int i = 0; i < HID; i += 4) {
        float4 w0 = *(const float4*)&sm->W[(i + 0) * HID + k0];
        float4 w1 = *(const float4*)&sm->W[(i + 1) * HID + k0];
        float4 w2 = *(const float4*)&sm->W[(i + 2) * HID + k0];
        float4 w3 = *(const float4*)&sm->W[(i + 3) * HID + k0];
#pragma unroll
        for (int r = 0; r < 4; r++) {
            float4 h = *(const float4*)&sm->H[(v0 + r) * HID + i];
            acc[r][0] = fmaf(h.x, w0.x, fmaf(h.y, w1.x, fmaf(h.z, w2.x, fmaf(h.w, w3.x, acc[r][0]))));
            acc[r][1] = fmaf(h.x, w0.y, fmaf(h.y, w1.y, fmaf(h.z, w2.y, fmaf(h.w, w3.y, acc[r][1]))));
            acc[r][2] = fmaf(h.x, w0.z, fmaf(h.y, w1.z, fmaf(h.z, w2.z, fmaf(h.w, w3.z, acc[r][2]))));
            acc[r][3] = fmaf(h.x, w0.w, fmaf(h.y, w1.w, fmaf(h.z, w2.w, fmaf(h.w, w3.w, acc[r][3]))));
        }
    }
#pragma unroll
    for (int r = 0; r < 4; r++)
        *(float4*)&sm->A[(v0 + r) * HID + k0] = make_float4(acc[r][0], acc[r][1], acc[r][2], acc[r][3]);
}

// ---- one GATConv layer (with self-loops), fully in SMEM ----
__device__ void gat_layer(SM* sm, const float* __restrict__ Wg,
                          const float* __restrict__ as_, const float* __restrict__ ad_,
                          const float* __restrict__ bias,
                          int tid, int wid, int lane)
{
    for (int i = tid; i < HID * HID; i += GT) sm->W[i] = Wg[i];
    if (tid < HID) { sm->vec0[tid] = as_[tid]; sm->vec1[tid] = ad_[tid]; sm->vec2[tid] = bias[tid]; }
    __syncthreads();

    gemm64(sm, tid);          // A = H @ W
    __syncthreads();

    // per-node attention scalars
    for (int v = wid; v < NPG; v += NW) {
        float2 x = *(const float2*)&sm->A[v * HID + lane * 2];
        float2 s2 = *(const float2*)&sm->vec0[lane * 2];
        float2 d2 = *(const float2*)&sm->vec1[lane * 2];
        float ps = wsum(x.x * s2.x + x.y * s2.y);
        float pd = wsum(x.x * d2.x + x.y * d2.y);
        if (lane == 0) { sm->alS[v] = ps; sm->alD[v] = pd; }
    }
    __syncthreads();

    // edge logits in CSR order
    for (int i = tid; i < EPG; i += GT)
        sm->e[i] = lrelu(sm->alS[sm->csrc[i]] + sm->alD[sm->cdst[i]], 0.2f);
    __syncthreads();

    // fused segment-softmax + aggregate (warp per destination node)
    for (int v = wid; v < NPG; v += NW) {
        int o0 = sm->off[v], o1 = sm->off[v + 1];
        float m = -3.4e38f;
        for (int j = o0 + lane; j < o1; j += 32) m = fmaxf(m, sm->e[j]);
        m = wmax(m);
        float lp = lrelu(sm->alS[v] + sm->alD[v], 0.2f);
        m = fmaxf(m, lp);
        float ps = 0.f;
        for (int j = o0 + lane; j < o1; j += 32) {
            float ex = expf(sm->e[j] - m);
            sm->e[j] = ex;
            ps += ex;
        }
        ps = wsum(ps);
        float exl = expf(lp - m);
        float inv = 1.f / (ps + exl + 1e-16f);
        __syncwarp();
        float2 acc = make_float2(0.f, 0.f);
        for (int j = o0; j < o1; j++) {
            float a = sm->e[j];
            int s = sm->csrc[j];
            float2 h = *(const float2*)&sm->A[s * HID + lane * 2];
            acc.x = fmaf(a, h.x, acc.x);
            acc.y = fmaf(a, h.y, acc.y);
        }
        float2 hv = *(const float2*)&sm->A[v * HID + lane * 2];
        acc.x = fmaf(exl, hv.x, acc.x);
        acc.y = fmaf(exl, hv.y, acc.y);
        float2 b2 = *(const float2*)&sm->vec2[lane * 2];
        float2 o;
        o.x = fmaxf(fmaf(acc.x, inv, b2.x), 0.f);
        o.y = fmaxf(fmaf(acc.y, inv, b2.y), 0.f);
        *(float2*)&sm->H[v * HID + lane * 2] = o;
    }
    __syncthreads();
}

// ---- kernel 1: full 3-layer GNN, one CTA per graph, 2 CTAs/SM ----
__global__ void __launch_bounds__(GT, 2) gnn_kernel(
    const float* __restrict__ x, const int* __restrict__ ei,
    const float* __restrict__ Wl, const float* __restrict__ bl,
    const float* __restrict__ Wr, const float* __restrict__ br,
    const float* __restrict__ attv, const float* __restrict__ bv2,
    const float* __restrict__ Wg1, const float* __restrict__ as1,
    const float* __restrict__ ad1, const float* __restrict__ bg1,
    const float* __restrict__ Wg2, const float* __restrict__ as2,
    const float* __restrict__ ad2, const float* __restrict__ bg2,
    const float* __restrict__ lngp, const float* __restrict__ lnbp)
{
    extern __shared__ char smraw[];
    SM* sm = (SM*)smraw;
    int tid = threadIdx.x, lane = tid & 31, wid = tid >> 5;
    int g = blockIdx.x, base = g * NPG;
    const int* srcp = ei + (size_t)g * EPG;
    const int* dstp = ei + (size_t)NGRAPH * EPG + (size_t)g * EPG;

    // ---- load inputs, count in-degrees ----
    for (int i = tid; i < NPG * 4; i += GT) sm->xin[i] = x[(size_t)base * 4 + i];
    if (tid < HID) { sm->lng[tid] = lngp[tid]; sm->lnb[tid] = lnbp[tid]; }
    for (int i = tid; i < NPG; i += GT) sm->cnt[i] = 0;
    __syncthreads();
    for (int i = tid; i < EPG; i += GT) atomicAdd(&sm->cnt[dstp[i] - base], 1);
    __syncthreads();

    // exclusive scan of counts -> off
    int myv = 0, sc = 0;
    if (tid < NPG) {
        myv = sm->cnt[tid]; sc = myv;
#pragma unroll
        for (int o = 1; o < 32; o <<= 1) {
            int n = __shfl_up_sync(0xffffffffu, sc, o);
            if (lane >= o) sc += n;
        }
        if (lane == 31) sm->scanw[wid] = sc;
    }
    __syncthreads();
    if (tid < NPG) {
        int add = 0;
        for (int i = 0; i < wid; i++) add += sm->scanw[i];
        sm->off[tid] = add + sc - myv;
    }
    if (tid == 0) sm->off[NPG] = EPG;
    __syncthreads();
    if (tid < NPG) sm->cnt[tid] = sm->off[tid];
    __syncthreads();
    // scatter into materialized CSR
    for (int i = tid; i < EPG; i += GT) {
        int s = srcp[i] - base, d = dstp[i] - base;
        int pos = atomicAdd(&sm->cnt[d], 1);
        sm->csrc[pos] = (unsigned char)s;
        sm->cdst[pos] = (unsigned char)d;
    }

    // ---- GATv2 layer ----
    for (int i = tid; i < 4 * HID; i += GT) { sm->W[i] = Wl[i]; sm->W[4 * HID + i] = Wr[i]; }
    if (tid < HID) { sm->vec0[tid] = bl[tid]; sm->vec1[tid] = br[tid];
                     sm->vec2[tid] = attv[tid]; sm->vec3[tid] = bv2[tid]; }
    __syncthreads();
    {   // xl -> A, xr -> H
        int k = tid & (HID - 1), vg = tid >> 6;
#pragma unroll 4
        for (int r = 0; r < 16; r++) {
            int v = vg * 16 + r;
            float a = sm->vec0[k], b = sm->vec1[k];
#pragma unroll
            for (int i = 0; i < 4; i++) {
                float xv = sm->xin[v * 4 + i];
                a = fmaf(xv, sm->W[i * HID + k], a);
                b = fmaf(xv, sm->W[4 * HID + i * HID + k], b);
            }
            sm->A[v * HID + k] = a;
            sm->H[v * HID + k] = b;
        }
    }
    __syncthreads();
    // edge logits in CSR order: e = lrelu(xl[s] + xr[d], 0.2) . att  (warp per edge)
    {
        float2 at = *(const float2*)&sm->vec2[lane * 2];
        for (int j = wid; j < EPG; j += NW) {
            int s = sm->csrc[j], d = sm->cdst[j];
            float2 xl = *(const float2*)&sm->A[s * HID + lane * 2];
            float2 xr = *(const float2*)&sm->H[d * HID + lane * 2];
            float t = lrelu(xl.x + xr.x, 0.2f) * at.x + lrelu(xl.y + xr.y, 0.2f) * at.y;
            t = wsum(t);
            if (lane == 0) sm->e[j] = t;
        }
    }
    __syncthreads();
    // fused softmax + aggregate + bias + lrelu(0.01) + layernorm -> H
    for (int v = wid; v < NPG; v += NW) {
        int o0 = sm->off[v], o1 = sm->off[v + 1];
        float m = -3.4e38f;
        for (int j = o0 + lane; j < o1; j += 32) m = fmaxf(m, sm->e[j]);
        m = wmax(m);
        float ps = 0.f;
        for (int j = o0 + lane; j < o1; j += 32) {
            float ex = expf(sm->e[j] - m);
            sm->e[j] = ex;
            ps += ex;
        }
        ps = wsum(ps);
        float inv = 1.f / (ps + 1e-16f);
        __syncwarp();
        float2 acc = make_float2(0.f, 0.f);
        for (int j = o0; j < o1; j++) {
            float a = sm->e[j];
            int s = sm->csrc[j];
            float2 h = *(const float2*)&sm->A[s * HID + lane * 2];
            acc.x = fmaf(a, h.x, acc.x);
            acc.y = fmaf(a, h.y, acc.y);
        }
        float2 b2 = *(const float2*)&sm->vec3[lane * 2];
        float t0 = lrelu(fmaf(acc.x, inv, b2.x), 0.01f);
        float t1 = lrelu(fmaf(acc.y, inv, b2.y), 0.01f);
        float mean = wsum(t0 + t1) * (1.f / 64.f);
        float d0 = t0 - mean, d1 = t1 - mean;
        float var = wsum(d0 * d0 + d1 * d1) * (1.f / 64.f);
        float rstd = rsqrtf(var + 1e-5f);
        float2 gg = *(const float2*)&sm->lng[lane * 2];
        float2 bb = *(const float2*)&sm->lnb[lane * 2];
        float2 o;
        o.x = fmaf(d0 * rstd, gg.x, bb.x);
        o.y = fmaf(d1 * rstd, gg.y, bb.y);
        *(float2*)&sm->H[v * HID + lane * 2] = o;
    }
    __syncthreads();

    // ---- GAT layers 1 & 2 ----
    gat_layer(sm, Wg1, as1, ad1, bg1, tid, wid, lane);
    gat_layer(sm, Wg2, as2, ad2, bg2, tid, wid, lane);

    // ---- write final features ----
    const float4* Hv = (const float4*)sm->H;
    float4* outp = (float4*)(g_h + (size_t)g * NPG * HID);
    for (int i = tid; i < NPG * HID / 4; i += GT) outp[i] = Hv[i];
}

// ---- kernel 2a: init h1 with bias ----
__global__ void init_h1(const float* __restrict__ b1)
{
    int i = blockIdx.x * blockDim.x + threadIdx.x;
    if (i < NGRAPH * 128) g_h1[i] = b1[i & 127];
}

// ---- kernel 2b: split-K GEMM  h1 += h[1024,8192] @ W1[8192,128] ----
__global__ void __launch_bounds__(256) head_gemm(const float* __restrict__ W1)
{
    __shared__ float As[64][16];
    __shared__ float Bs[16][128];
    int m0 = blockIdx.x * 64;
    int kbase = blockIdx.y * 512;
    int tid = threadIdx.x;
    int tx = tid & 15, ty = tid >> 4;
    int r0 = ty * 4, c0 = tx * 8;
    float acc[4][8];
#pragma unroll
    for (int r = 0; r < 4; r++)
#pragma unroll
        for (int c = 0; c < 8; c++) acc[r][c] = 0.f;

    int ar = tid >> 2, aq = (tid & 3) * 4;
    int brr = tid >> 4, bc = (tid & 15) * 8;
    for (int kk = kbase; kk < kbase + 512; kk += 16) {
        *(float4*)&As[ar][aq]      = *(const float4*)&g_h[(size_t)(m0 + ar) * 8192 + kk + aq];
        *(float4*)&Bs[brr][bc]     = *(const float4*)&W1[(size_t)(kk + brr) * 128 + bc];
        *(float4*)&Bs[brr][bc + 4] = *(const float4*)&W1[(size_t)(kk + brr) * 128 + bc + 4];
        __syncthreads();
#pragma unroll
        for (int k = 0; k < 16; k++) {
            float a0 = As[r0][k], a1 = As[r0 + 1][k], a2 = As[r0 + 2][k], a3 = As[r0 + 3][k];
            float4 bA = *(float4*)&Bs[k][c0];
            float4 bB = *(float4*)&Bs[k][c0 + 4];
            acc[0][0] = fmaf(a0, bA.x, acc[0][0]); acc[0][1] = fmaf(a0, bA.y, acc[0][1]);
            acc[0][2] = fmaf(a0, bA.z, acc[0][2]); acc[0][3] = fmaf(a0, bA.w, acc[0][3]);
            acc[0][4] = fmaf(a0, bB.x, acc[0][4]); acc[0][5] = fmaf(a0, bB.y, acc[0][5]);
            acc[0][6] = fmaf(a0, bB.z, acc[0][6]); acc[0][7] = fmaf(a0, bB.w, acc[0][7]);
            acc[1][0] = fmaf(a1, bA.x, acc[1][0]); acc[1][1] = fmaf(a1, bA.y, acc[1][1]);
            acc[1][2] = fmaf(a1, bA.z, acc[1][2]); acc[1][3] = fmaf(a1, bA.w, acc[1][3]);
            acc[1][4] = fmaf(a1, bB.x, acc[1][4]); acc[1][5] = fmaf(a1, bB.y, acc[1][5]);
            acc[1][6] = fmaf(a1, bB.z, acc[1][6]); acc[1][7] = fmaf(a1, bB.w, acc[1][7]);
            acc[2][0] = fmaf(a2, bA.x, acc[2][0]); acc[2][1] = fmaf(a2, bA.y, acc[2][1]);
            acc[2][2] = fmaf(a2, bA.z, acc[2][2]); acc[2][3] = fmaf(a2, bA.w, acc[2][3]);
            acc[2][4] = fmaf(a2, bB.x, acc[2][4]); acc[2][5] = fmaf(a2, bB.y, acc[2][5]);
            acc[2][6] = fmaf(a2, bB.z, acc[2][6]); acc[2][7] = fmaf(a2, bB.w, acc[2][7]);
            acc[3][0] = fmaf(a3, bA.x, acc[3][0]); acc[3][1] = fmaf(a3, bA.y, acc[3][1]);
            acc[3][2] = fmaf(a3, bA.z, acc[3][2]); acc[3][3] = fmaf(a3, bA.w, acc[3][3]);
            acc[3][4] = fmaf(a3, bB.x, acc[3][4]); acc[3][5] = fmaf(a3, bB.y, acc[3][5]);
            acc[3][6] = fmaf(a3, bB.z, acc[3][6]); acc[3][7] = fmaf(a3, bB.w, acc[3][7]);
        }
        __syncthreads();
    }
#pragma unroll
    for (int r = 0; r < 4; r++)
#pragma unroll
        for (int c = 0; c < 8; c++)
            atomicAdd(&g_h1[(m0 + r0 + r) * 128 + c0 + c], acc[r][c]);
}

// ---- kernel 3: out = sigmoid(lrelu(h1,0.01) @ W2 + b2), one warp per graph ----
__global__ void head_final(const float* __restrict__ W2, const float* __restrict__ b2,
                           float* __restrict__ outp)
{
    int g = blockIdx.x * 8 + (threadIdx.x >> 5);
    int lane = threadIdx.x & 31;
    float4 h = *(const float4*)&g_h1[g * 128 + lane * 4];
    h.x = lrelu(h.x, 0.01f); h.y = lrelu(h.y, 0.01f);
    h.z = lrelu(h.z, 0.01f); h.w = lrelu(h.w, 0.01f);
    float4 w = *(const float4*)&W2[lane * 4];
    float p = h.x * w.x + h.y * w.y + h.z * w.z + h.w * w.w;
    p = wsum(p);
    if (lane == 0) outp[g] = 1.f / (1.f + expf(-(p + b2[0])));
}

extern "C" void kernel_launch(void* const* d_in, const int* in_sizes, int n_in,
                              void* d_out, int out_size)
{
    const float* x    = (const float*)d_in[0];
    const int*   ei   = (const int*)  d_in[1];
    const float* Wl   = (const float*)d_in[2];
    const float* bl   = (const float*)d_in[3];
    const float* Wr   = (const float*)d_in[4];
    const float* br   = (const float*)d_in[5];
    const float* attv = (const float*)d_in[6];
    const float* bv2  = (const float*)d_in[7];
    const float* Wg1  = (const float*)d_in[8];
    const float* as1  = (const float*)d_in[9];
    const float* ad1  = (const float*)d_in[10];
    const float* bg1  = (const float*)d_in[11];
    const float* Wg2  = (const float*)d_in[12];
    const float* as2  = (const float*)d_in[13];
    const float* ad2  = (const float*)d_in[14];
    const float* bg2  = (const float*)d_in[15];
    const float* lng  = (const float*)d_in[16];
    const float* lnb  = (const float*)d_in[17];
    const float* W1   = (const float*)d_in[18];
    const float* b1   = (const float*)d_in[19];
    const float* W2   = (const float*)d_in[20];
    const float* b2   = (const float*)d_in[21];
    float* outp = (float*)d_out;

    int smem = (int)sizeof(SM);
    cudaFuncSetAttribute(gnn_kernel, cudaFuncAttributeMaxDynamicSharedMemorySize, smem);

    gnn_kernel<<<NGRAPH, GT, smem>>>(x, ei, Wl, bl, Wr, br, attv, bv2,
                                     Wg1, as1, ad1, bg1, Wg2, as2, ad2, bg2, lng, lnb);
    init_h1<<<(NGRAPH * 128 + 255) / 256, 256>>>(b1);
    head_gemm<<<dim3(16, 16), 256>>>(W1);
    head_final<<<NGRAPH / 8, 256>>>(W2, b2, outp);
}

// round 6
// speedup vs baseline: 1.6844x; 1.2190x over previous
#include <cuda_runtime.h>

#define NGRAPH 1024
#define NPG    128
#define HID    64
#define EPG    2048            // edges per graph (NPG*16)
#define GT     512             // threads in GNN kernel
#define NW     (GT/32)         // 16 warps

typedef unsigned long long ull;

// ---- f32x2 packed-FMA helpers (sm_100+; FFMA2 not emitted by ptxas from C++) ----
__device__ __forceinline__ ull pk1(float x) {
    ull r; asm("mov.b64 %0,{%1,%1};" : "=l"(r) : "f"(x)); return r;
}
__device__ __forceinline__ void fma2(ull& d, ull a, ull b) {
    asm("fma.rn.f32x2 %0,%1,%2,%0;" : "+l"(d) : "l"(a), "l"(b));
}
__device__ __forceinline__ float2 unpk(ull v) {
    float2 r; asm("mov.b64 {%0,%1},%2;" : "=f"(r.x), "=f"(r.y) : "l"(v)); return r;
}

// ---- global scratch ----
__device__ float g_h [(size_t)NGRAPH * NPG * HID];   // final node features [N,64]
__device__ float g_h1[NGRAPH * 128];                 // head hidden [1024,128]

// ---- shared memory (~108.6KB -> 2 CTAs/SM) ----
struct SM {
    float  H[NPG * HID];       // 32KB node features (also xr in GATv2)
    float  A[NPG * HID];       // 32KB xl / xw
    float  W[HID * HID];       // 16KB weight tile
    float2 ae[EPG];            // 16KB CSR-ordered {exp(logit) or logit, src-bits}
    float  xin[NPG * 4];       //  2KB
    float  vec0[HID], vec1[HID], vec2[HID], vec3[HID];
    float  lng[HID], lnb[HID];
    float  alS[NPG], alD[NPG], alE[NPG];
    int    off[NPG + 1];
    int    cnt[NPG];
    int    scanw[4];
    unsigned char csrc[EPG], cdst[EPG];
};

__device__ __forceinline__ float wsum(float v) {
#pragma unroll
    for (int o = 16; o; o >>= 1) v += __shfl_xor_sync(0xffffffffu, v, o);
    return v;
}

// 64x64 GEMM: A = H @ W. Warp w owns rows 8w..8w+7; lane owns col pair (2l,2l+1).
// H rows read as float4 broadcasts (1-cyc crossbar), W pairs as direct b64 loads.
__device__ __forceinline__ void gemm64_warp(SM* sm, int wid, int lane)
{
    int r0 = wid * 8;
    ull acc[8];
#pragma unroll
    for (int r = 0; r < 8; r++) acc[r] = 0ull;
    const float* Wb = sm->W + lane * 2;
#pragma unroll 2
    for (int k = 0; k < HID; k += 4) {
        ull w0 = *(const ull*)&Wb[(k + 0) * HID];
        ull w1 = *(const ull*)&Wb[(k + 1) * HID];
        ull w2 = *(const ull*)&Wb[(k + 2) * HID];
        ull w3 = *(const ull*)&Wb[(k + 3) * HID];
#pragma unroll
        for (int r = 0; r < 8; r++) {
            float4 h = *(const float4*)&sm->H[(r0 + r) * HID + k];
            fma2(acc[r], pk1(h.x), w0);
            fma2(acc[r], pk1(h.y), w1);
            fma2(acc[r], pk1(h.z), w2);
            fma2(acc[r], pk1(h.w), w3);
        }
    }
#pragma unroll
    for (int r = 0; r < 8; r++)
        *(ull*)&sm->A[(r0 + r) * HID + lane * 2] = acc[r];
}

// ---- one GATConv layer (with self-loops), fully in SMEM ----
__device__ void gat_layer(SM* sm, const float* __restrict__ Wg,
                          const float* __restrict__ as_, const float* __restrict__ ad_,
                          const float* __restrict__ bias,
                          int tid, int wid, int lane)
{
    for (int i = tid; i < HID * HID; i += GT) sm->W[i] = Wg[i];
    if (tid < HID) { sm->vec0[tid] = as_[tid]; sm->vec1[tid] = ad_[tid]; sm->vec2[tid] = bias[tid]; }
    __syncthreads();

    gemm64_warp(sm, wid, lane);     // A = H @ W
    __syncthreads();

    // per-node attention scalars
    for (int v = wid; v < NPG; v += NW) {
        float2 x  = *(const float2*)&sm->A[v * HID + lane * 2];
        float2 s2 = *(const float2*)&sm->vec0[lane * 2];
        float2 d2 = *(const float2*)&sm->vec1[lane * 2];
        float ps = wsum(x.x * s2.x + x.y * s2.y);
        float pd = wsum(x.x * d2.x + x.y * d2.y);
        if (lane == 0) { sm->alS[v] = ps; sm->alD[v] = pd; }
    }
    __syncthreads();

    // self-loop exp (node-parallel) + fused logit+exp pass (edge-parallel)
    if (tid < NPG) {
        float t = sm->alS[tid] + sm->alD[tid];
        sm->alE[tid] = __expf(fmaf(0.4f, fabsf(t), 0.6f * t));   // lrelu(t,0.2)
    }
    for (int i = tid; i < EPG; i += GT) {
        int s = sm->csrc[i], d = sm->cdst[i];
        float t = sm->alS[s] + sm->alD[d];
        float2 w;
        w.x = __expf(fmaf(0.4f, fabsf(t), 0.6f * t));
        w.y = __int_as_float(s);
        sm->ae[i] = w;
    }
    __syncthreads();

    // single-pass aggregate + normalize (warp per destination)
    for (int v = wid; v < NPG; v += NW) {
        int o0 = sm->off[v], o1 = sm->off[v + 1];
        ull acc = 0ull; float ps = 0.f;
#pragma unroll 2
        for (int j = o0; j < o1; j++) {
            float2 t = sm->ae[j];
            ull hv = *(const ull*)&sm->A[__float_as_int(t.y) * HID + lane * 2];
            fma2(acc, pk1(t.x), hv);
            ps += t.x;
        }
        float el = sm->alE[v];
        fma2(acc, pk1(el), *(const ull*)&sm->A[v * HID + lane * 2]);
        float inv = __fdividef(1.f, ps + el + 1e-16f);
        float2 r  = unpk(acc);
        float2 b2 = *(const float2*)&sm->vec2[lane * 2];
        float2 o;
        o.x = fmaxf(fmaf(r.x, inv, b2.x), 0.f);
        o.y = fmaxf(fmaf(r.y, inv, b2.y), 0.f);
        *(float2*)&sm->H[v * HID + lane * 2] = o;
    }
    __syncthreads();
}

// ---- kernel 1: full 3-layer GNN, one CTA per graph, 2 CTAs/SM ----
__global__ void __launch_bounds__(GT, 2) gnn_kernel(
    const float* __restrict__ x, const int* __restrict__ ei,
    const float* __restrict__ Wl, const float* __restrict__ bl,
    const float* __restrict__ Wr, const float* __restrict__ br,
    const float* __restrict__ attv, const float* __restrict__ bv2,
    const float* __restrict__ Wg1, const float* __restrict__ as1,
    const float* __restrict__ ad1, const float* __restrict__ bg1,
    const float* __restrict__ Wg2, const float* __restrict__ as2,
    const float* __restrict__ ad2, const float* __restrict__ bg2,
    const float* __restrict__ lngp, const float* __restrict__ lnbp)
{
    extern __shared__ char smraw[];
    SM* sm = (SM*)smraw;
    int tid = threadIdx.x, lane = tid & 31, wid = tid >> 5;
    int g = blockIdx.x, base = g * NPG;
    const int* srcp = ei + (size_t)g * EPG;
    const int* dstp = ei + (size_t)NGRAPH * EPG + (size_t)g * EPG;

    // ---- load inputs, count in-degrees ----
    for (int i = tid; i < NPG * 4; i += GT) sm->xin[i] = x[(size_t)base * 4 + i];
    if (tid < HID) { sm->lng[tid] = lngp[tid]; sm->lnb[tid] = lnbp[tid]; }
    for (int i = tid; i < NPG; i += GT) sm->cnt[i] = 0;
    __syncthreads();
    for (int i = tid; i < EPG; i += GT) atomicAdd(&sm->cnt[dstp[i] - base], 1);
    __syncthreads();

    // exclusive scan of counts -> off
    int myv = 0, sc = 0;
    if (tid < NPG) {
        myv = sm->cnt[tid]; sc = myv;
#pragma unroll
        for (int o = 1; o < 32; o <<= 1) {
            int n = __shfl_up_sync(0xffffffffu, sc, o);
            if (lane >= o) sc += n;
        }
        if (lane == 31) sm->scanw[wid] = sc;
    }
    __syncthreads();
    if (tid < NPG) {
        int add = 0;
        for (int i = 0; i < wid; i++) add += sm->scanw[i];
        sm->off[tid] = add + sc - myv;
    }
    if (tid == 0) sm->off[NPG] = EPG;
    __syncthreads();
    if (tid < NPG) sm->cnt[tid] = sm->off[tid];
    __syncthreads();
    // scatter into materialized CSR
    for (int i = tid; i < EPG; i += GT) {
        int s = srcp[i] - base, d = dstp[i] - base;
        int pos = atomicAdd(&sm->cnt[d], 1);
        sm->csrc[pos] = (unsigned char)s;
        sm->cdst[pos] = (unsigned char)d;
    }

    // ---- GATv2 layer ----
    for (int i = tid; i < 4 * HID; i += GT) { sm->W[i] = Wl[i]; sm->W[4 * HID + i] = Wr[i]; }
    if (tid < HID) { sm->vec0[tid] = bl[tid]; sm->vec1[tid] = br[tid];
                     sm->vec2[tid] = attv[tid]; sm->vec3[tid] = bv2[tid]; }
    __syncthreads();
    {   // xl -> A, xr -> H  (IN = 4, tiny)
        int k = tid & (HID - 1), vg = tid >> 6;
#pragma unroll 4
        for (int r = 0; r < 16; r++) {
            int v = vg * 16 + r;
            float a = sm->vec0[k], b = sm->vec1[k];
#pragma unroll
            for (int i = 0; i < 4; i++) {
                float xv = sm->xin[v * 4 + i];
                a = fmaf(xv, sm->W[i * HID + k], a);
                b = fmaf(xv, sm->W[4 * HID + i * HID + k], b);
            }
            sm->A[v * HID + k] = a;
            sm->H[v * HID + k] = b;
        }
    }
    __syncthreads();
    // v2 logits: half-warp per edge, lrelu(s)*a = 0.6*s*a + 0.4*|s|*a
    {
        int hl = lane & 15;
        float4 at = *(const float4*)&sm->vec2[hl * 4];
        for (int j = wid * 2 + (lane >> 4); j < EPG; j += NW * 2) {
            int s = sm->csrc[j], d = sm->cdst[j];
            float4 xl = *(const float4*)&sm->A[s * HID + hl * 4];
            float4 xr = *(const float4*)&sm->H[d * HID + hl * 4];
            float s0 = xl.x + xr.x, s1 = xl.y + xr.y, s2 = xl.z + xr.z, s3 = xl.w + xr.w;
            float p = fmaf(s0, at.x, fmaf(s1, at.y, fmaf(s2, at.z, s3 * at.w)));
            float q = fmaf(fabsf(s0), at.x, fmaf(fabsf(s1), at.y,
                      fmaf(fabsf(s2), at.z, fabsf(s3) * at.w)));
            float t = fmaf(0.4f, q, 0.6f * p);
#pragma unroll
            for (int o = 8; o; o >>= 1) t += __shfl_xor_sync(0xffffffffu, t, o);
            if (hl == 0) sm->ae[j].x = t;
        }
    }
    __syncthreads();
    // exp pass (edge-parallel)
    for (int i = tid; i < EPG; i += GT) {
        float2 w;
        w.x = __expf(sm->ae[i].x);
        w.y = __int_as_float((int)sm->csrc[i]);
        sm->ae[i] = w;
    }
    __syncthreads();
    // aggregate + bias + lrelu(0.01) + layernorm -> H   (no self-loop in GATv2)
    for (int v = wid; v < NPG; v += NW) {
        int o0 = sm->off[v], o1 = sm->off[v + 1];
        ull acc = 0ull; float ps = 0.f;
#pragma unroll 2
        for (int j = o0; j < o1; j++) {
            float2 t = sm->ae[j];
            ull hv = *(const ull*)&sm->A[__float_as_int(t.y) * HID + lane * 2];
            fma2(acc, pk1(t.x), hv);
            ps += t.x;
        }
        float inv = __fdividef(1.f, ps + 1e-16f);
        float2 r  = unpk(acc);
        float2 b2 = *(const float2*)&sm->vec3[lane * 2];
        float u0 = fmaf(r.x, inv, b2.x);
        float u1 = fmaf(r.y, inv, b2.y);
        float t0 = fmaf(0.495f, fabsf(u0), 0.505f * u0);   // lrelu 0.01
        float t1 = fmaf(0.495f, fabsf(u1), 0.505f * u1);
        float mean = wsum(t0 + t1) * (1.f / 64.f);
        float d0 = t0 - mean, d1 = t1 - mean;
        float var = wsum(d0 * d0 + d1 * d1) * (1.f / 64.f);
        float rstd = rsqrtf(var + 1e-5f);
        float2 gg = *(const float2*)&sm->lng[lane * 2];
        float2 bb = *(const float2*)&sm->lnb[lane * 2];
        float2 o;
        o.x = fmaf(d0 * rstd, gg.x, bb.x);
        o.y = fmaf(d1 * rstd, gg.y, bb.y);
        *(float2*)&sm->H[v * HID + lane * 2] = o;
    }
    __syncthreads();

    // ---- GAT layers 1 & 2 ----
    gat_layer(sm, Wg1, as1, ad1, bg1, tid, wid, lane);
    gat_layer(sm, Wg2, as2, ad2, bg2, tid, wid, lane);

    // ---- write final features ----
    const float4* Hv = (const float4*)sm->H;
    float4* outp = (float4*)(g_h + (size_t)g * NPG * HID);
    for (int i = tid; i < NPG * HID / 4; i += GT) outp[i] = Hv[i];
}

// ---- kernel 2a: init h1 with bias ----
__global__ void init_h1(const float* __restrict__ b1)
{
    int i = blockIdx.x * blockDim.x + threadIdx.x;
    if (i < NGRAPH * 128) g_h1[i] = b1[i & 127];
}

// ---- kernel 2b: split-K GEMM  h1 += h[1024,8192] @ W1[8192,128], FFMA2 inner ----
__global__ void __launch_bounds__(256) head_gemm(const float* __restrict__ W1)
{
    __shared__ float As[64][16];
    __shared__ float Bs[16][128];
    int m0 = blockIdx.x * 64;
    int kbase = blockIdx.y * 256;
    int tid = threadIdx.x;
    int tx = tid & 15, ty = tid >> 4;
    int r0 = ty * 4, c0 = tx * 8;
    ull acc[4][4];
#pragma unroll
    for (int r = 0; r < 4; r++)
#pragma unroll
        for (int c = 0; c < 4; c++) acc[r][c] = 0ull;

    int ar = tid >> 2, aq = (tid & 3) * 4;
    int brr = tid >> 4, bc = (tid & 15) * 8;
    for (int kk = kbase; kk < kbase + 256; kk += 16) {
        *(float4*)&As[ar][aq]      = *(const float4*)&g_h[(size_t)(m0 + ar) * 8192 + kk + aq];
        *(float4*)&Bs[brr][bc]     = *(const float4*)&W1[(size_t)(kk + brr) * 128 + bc];
        *(float4*)&Bs[brr][bc + 4] = *(const float4*)&W1[(size_t)(kk + brr) * 128 + bc + 4];
        __syncthreads();
#pragma unroll
        for (int k = 0; k < 16; k++) {
            ull a0 = pk1(As[r0][k]),     a1 = pk1(As[r0 + 1][k]);
            ull a2 = pk1(As[r0 + 2][k]), a3 = pk1(As[r0 + 3][k]);
            ull b0 = *(const ull*)&Bs[k][c0];
            ull b1 = *(const ull*)&Bs[k][c0 + 2];
            ull b2 = *(const ull*)&Bs[k][c0 + 4];
            ull b3 = *(const ull*)&Bs[k][c0 + 6];
            fma2(acc[0][0], a0, b0); fma2(acc[0][1], a0, b1); fma2(acc[0][2], a0, b2); fma2(acc[0][3], a0, b3);
            fma2(acc[1][0], a1, b0); fma2(acc[1][1], a1, b1); fma2(acc[1][2], a1, b2); fma2(acc[1][3], a1, b3);
            fma2(acc[2][0], a2, b0); fma2(acc[2][1], a2, b1); fma2(acc[2][2], a2, b2); fma2(acc[2][3], a2, b3);
            fma2(acc[3][0], a3, b0); fma2(acc[3][1], a3, b1); fma2(acc[3][2], a3, b2); fma2(acc[3][3], a3, b3);
        }
        __syncthreads();
    }
#pragma unroll
    for (int r = 0; r < 4; r++)
#pragma unroll
        for (int c = 0; c < 4; c++) {
            float2 p = unpk(acc[r][c]);
            atomicAdd(&g_h1[(m0 + r0 + r) * 128 + c0 + 2 * c],     p.x);
            atomicAdd(&g_h1[(m0 + r0 + r) * 128 + c0 + 2 * c + 1], p.y);
        }
}

// ---- kernel 3: out = sigmoid(lrelu(h1,0.01) @ W2 + b2), one warp per graph ----
__global__ void head_final(const float* __restrict__ W2, const float* __restrict__ b2,
                           float* __restrict__ outp)
{
    int g = blockIdx.x * 8 + (threadIdx.x >> 5);
    int lane = threadIdx.x & 31;
    float4 h = *(const float4*)&g_h1[g * 128 + lane * 4];
    h.x = fmaf(0.495f, fabsf(h.x), 0.505f * h.x);
    h.y = fmaf(0.495f, fabsf(h.y), 0.505f * h.y);
    h.z = fmaf(0.495f, fabsf(h.z), 0.505f * h.z);
    h.w = fmaf(0.495f, fabsf(h.w), 0.505f * h.w);
    float4 w = *(const float4*)&W2[lane * 4];
    float p = h.x * w.x + h.y * w.y + h.z * w.z + h.w * w.w;
    p = wsum(p);
    if (lane == 0) outp[g] = 1.f / (1.f + expf(-(p + b2[0])));
}

extern "C" void kernel_launch(void* const* d_in, const int* in_sizes, int n_in,
                              void* d_out, int out_size)
{
    const float* x    = (const float*)d_in[0];
    const int*   ei   = (const int*)  d_in[1];
    const float* Wl   = (const float*)d_in[2];
    const float* bl   = (const float*)d_in[3];
    const float* Wr   = (const float*)d_in[4];
    const float* br   = (const float*)d_in[5];
    const float* attv = (const float*)d_in[6];
    const float* bv2  = (const float*)d_in[7];
    const float* Wg1  = (const float*)d_in[8];
    const float* as1  = (const float*)d_in[9];
    const float* ad1  = (const float*)d_in[10];
    const float* bg1  = (const float*)d_in[11];
    const float* Wg2  = (const float*)d_in[12];
    const float* as2  = (const float*)d_in[13];
    const float* ad2  = (const float*)d_in[14];
    const float* bg2  = (const float*)d_in[15];
    const float* lng  = (const float*)d_in[16];
    const float* lnb  = (const float*)d_in[17];
    const float* W1   = (const float*)d_in[18];
    const float* b1   = (const float*)d_in[19];
    const float* W2   = (const float*)d_in[20];
    const float* b2   = (const float*)d_in[21];
    float* outp = (float*)d_out;

    int smem = (int)sizeof(SM);
    cudaFuncSetAttribute(gnn_kernel, cudaFuncAttributeMaxDynamicSharedMemorySize, smem);

    gnn_kernel<<<NGRAPH, GT, smem>>>(x, ei, Wl, bl, Wr, br, attv, bv2,
                                     Wg1, as1, ad1, bg1, Wg2, as2, ad2, bg2, lng, lnb);
    init_h1<<<(NGRAPH * 128 + 255) / 256, 256>>>(b1);
    head_gemm<<<dim3(16, 32), 256>>>(W1);
    head_final<<<NGRAPH / 8, 256>>>(W2, b2, outp);
}

// round 7
// speedup vs baseline: 1.6922x; 1.0046x over previous
#include <cuda_runtime.h>

#define NGRAPH 1024
#define NPG    128
#define HID    64
#define EPG    2048            // edges per graph (NPG*16)
#define GT     512             // threads in GNN kernel
#define NW     (GT/32)         // 16 warps
#define KSPLIT 32              // head gemm k-splits

typedef unsigned long long ull;

// ---- f32x2 packed-FMA helpers (sm_100+; FFMA2 not emitted by ptxas from C++) ----
__device__ __forceinline__ ull pk1(float x) {
    ull r; asm("mov.b64 %0,{%1,%1};" : "=l"(r) : "f"(x)); return r;
}
__device__ __forceinline__ void fma2(ull& d, ull a, ull b) {
    asm("fma.rn.f32x2 %0,%1,%2,%0;" : "+l"(d) : "l"(a), "l"(b));
}
__device__ __forceinline__ float2 unpk(ull v) {
    float2 r; asm("mov.b64 {%0,%1},%2;" : "=f"(r.x), "=f"(r.y) : "l"(v)); return r;
}

// ---- global scratch ----
__device__ float g_h [(size_t)NGRAPH * NPG * HID];        // final node features [1024x8192]
__device__ float g_hp[KSPLIT][(size_t)NGRAPH * 128];      // head GEMM k-split partials (16MB)

// ---- shared memory (~108.6KB -> 2 CTAs/SM) ----
struct SM {
    float  H[NPG * HID];       // 32KB node features (also xr in GATv2)
    float  A[NPG * HID];       // 32KB xl / xw
    float  W[HID * HID];       // 16KB weight tile
    float2 ae[EPG];            // 16KB CSR-ordered {exp(logit), src byte-ish offset}
    float  xin[NPG * 4];       //  2KB
    float  vec0[HID], vec1[HID], vec2[HID], vec3[HID];
    float  lng[HID], lnb[HID];
    float  alS[NPG], alD[NPG], alE[NPG];
    int    off[NPG + 1];
    int    cnt[NPG];
    int    scanw[4];
    unsigned char csrc[EPG], cdst[EPG];
};

__device__ __forceinline__ float wsum(float v) {
#pragma unroll
    for (int o = 16; o; o >>= 1) v += __shfl_xor_sync(0xffffffffu, v, o);
    return v;
}

// 64x64 GEMM (A = H @ W) with fused attention-scalar epilogue.
// Warp w owns rows 8w..8w+7; lane owns col pair (2l,2l+1).
// Epilogue: alS/alD/alE for the warp's 8 rows via ILP'd 16-reg butterfly.
__device__ __forceinline__ void gemm64_att(SM* sm, int wid, int lane)
{
    int r0 = wid * 8;
    ull acc[8];
#pragma unroll
    for (int r = 0; r < 8; r++) acc[r] = 0ull;
    const float* Wb = sm->W + lane * 2;
#pragma unroll 2
    for (int k = 0; k < HID; k += 4) {
        ull w0 = *(const ull*)&Wb[(k + 0) * HID];
        ull w1 = *(const ull*)&Wb[(k + 1) * HID];
        ull w2 = *(const ull*)&Wb[(k + 2) * HID];
        ull w3 = *(const ull*)&Wb[(k + 3) * HID];
#pragma unroll
        for (int r = 0; r < 8; r++) {
            float4 h = *(const float4*)&sm->H[(r0 + r) * HID + k];
            fma2(acc[r], pk1(h.x), w0);
            fma2(acc[r], pk1(h.y), w1);
            fma2(acc[r], pk1(h.z), w2);
            fma2(acc[r], pk1(h.w), w3);
        }
    }
    float2 s2 = *(const float2*)&sm->vec0[lane * 2];
    float2 d2 = *(const float2*)&sm->vec1[lane * 2];
    float ps[8], pd[8];
#pragma unroll
    for (int r = 0; r < 8; r++) {
        *(ull*)&sm->A[(r0 + r) * HID + lane * 2] = acc[r];
        float2 a = unpk(acc[r]);
        ps[r] = a.x * s2.x + a.y * s2.y;
        pd[r] = a.x * d2.x + a.y * d2.y;
    }
    // 16 independent butterflies, 5 stages, fully overlapped
#pragma unroll
    for (int o = 16; o; o >>= 1) {
#pragma unroll
        for (int r = 0; r < 8; r++) {
            ps[r] += __shfl_xor_sync(0xffffffffu, ps[r], o);
            pd[r] += __shfl_xor_sync(0xffffffffu, pd[r], o);
        }
    }
    if (lane < 8) {
        int v = r0 + lane;
        float a = ps[lane], b = pd[lane];
        sm->alS[v] = a;
        sm->alD[v] = b;
        float t = a + b;
        sm->alE[v] = __expf(fmaf(0.4f, fabsf(t), 0.6f * t));   // exp(lrelu(t,0.2))
    }
}

// ---- one GATConv layer (with self-loops), fully in SMEM ----
__device__ void gat_layer(SM* sm, const float* __restrict__ Wg,
                          const float* __restrict__ as_, const float* __restrict__ ad_,
                          const float* __restrict__ bias,
                          int tid, int wid, int lane)
{
    for (int i = tid; i < HID * HID; i += GT) sm->W[i] = Wg[i];
    if (tid < HID) { sm->vec0[tid] = as_[tid]; sm->vec1[tid] = ad_[tid]; sm->vec2[tid] = bias[tid]; }
    __syncthreads();

    gemm64_att(sm, wid, lane);     // A = H @ W, plus alS/alD/alE
    __syncthreads();

    // fused logit+exp pass (edge-parallel, 4 edges/thread)
#pragma unroll
    for (int i = tid; i < EPG; i += GT) {
        int s = sm->csrc[i], d = sm->cdst[i];
        float t = sm->alS[s] + sm->alD[d];
        float2 w;
        w.x = __expf(fmaf(0.4f, fabsf(t), 0.6f * t));
        w.y = __int_as_float(s * HID);
        sm->ae[i] = w;
    }
    __syncthreads();

    // single-pass aggregate + normalize (warp per destination)
    for (int v = wid; v < NPG; v += NW) {
        int o0 = sm->off[v], o1 = sm->off[v + 1];
        ull acc = 0ull; float ps = 0.f;
#pragma unroll 2
        for (int j = o0; j < o1; j++) {
            float2 t = sm->ae[j];
            ull hv = *(const ull*)&sm->A[__float_as_int(t.y) + lane * 2];
            fma2(acc, pk1(t.x), hv);
            ps += t.x;
        }
        float el = sm->alE[v];
        fma2(acc, pk1(el), *(const ull*)&sm->A[v * HID + lane * 2]);
        float inv = __fdividef(1.f, ps + el + 1e-16f);
        float2 r  = unpk(acc);
        float2 b2 = *(const float2*)&sm->vec2[lane * 2];
        float2 o;
        o.x = fmaxf(fmaf(r.x, inv, b2.x), 0.f);
        o.y = fmaxf(fmaf(r.y, inv, b2.y), 0.f);
        *(float2*)&sm->H[v * HID + lane * 2] = o;
    }
    __syncthreads();
}

// ---- kernel 1: full 3-layer GNN, one CTA per graph, 2 CTAs/SM ----
__global__ void __launch_bounds__(GT, 2) gnn_kernel(
    const float* __restrict__ x, const int* __restrict__ ei,
    const float* __restrict__ Wl, const float* __restrict__ bl,
    const float* __restrict__ Wr, const float* __restrict__ br,
    const float* __restrict__ attv, const float* __restrict__ bv2,
    const float* __restrict__ Wg1, const float* __restrict__ as1,
    const float* __restrict__ ad1, const float* __restrict__ bg1,
    const float* __restrict__ Wg2, const float* __restrict__ as2,
    const float* __restrict__ ad2, const float* __restrict__ bg2,
    const float* __restrict__ lngp, const float* __restrict__ lnbp)
{
    extern __shared__ char smraw[];
    SM* sm = (SM*)smraw;
    int tid = threadIdx.x, lane = tid & 31, wid = tid >> 5;
    int g = blockIdx.x, base = g * NPG;
    const int* srcp = ei + (size_t)g * EPG;
    const int* dstp = ei + (size_t)NGRAPH * EPG + (size_t)g * EPG;

    // ---- load inputs, count in-degrees ----
    for (int i = tid; i < NPG * 4; i += GT) sm->xin[i] = x[(size_t)base * 4 + i];
    if (tid < HID) { sm->lng[tid] = lngp[tid]; sm->lnb[tid] = lnbp[tid]; }
    for (int i = tid; i < NPG; i += GT) sm->cnt[i] = 0;
    __syncthreads();
    for (int i = tid; i < EPG; i += GT) atomicAdd(&sm->cnt[dstp[i] - base], 1);
    __syncthreads();

    // exclusive scan of counts -> off
    int myv = 0, sc = 0;
    if (tid < NPG) {
        myv = sm->cnt[tid]; sc = myv;
#pragma unroll
        for (int o = 1; o < 32; o <<= 1) {
            int n = __shfl_up_sync(0xffffffffu, sc, o);
            if (lane >= o) sc += n;
        }
        if (lane == 31) sm->scanw[wid] = sc;
    }
    __syncthreads();
    if (tid < NPG) {
        int add = 0;
        for (int i = 0; i < wid; i++) add += sm->scanw[i];
        sm->off[tid] = add + sc - myv;
    }
    if (tid == 0) sm->off[NPG] = EPG;
    __syncthreads();
    if (tid < NPG) sm->cnt[tid] = sm->off[tid];
    __syncthreads();
    // scatter into materialized CSR
    for (int i = tid; i < EPG; i += GT) {
        int s = srcp[i] - base, d = dstp[i] - base;
        int pos = atomicAdd(&sm->cnt[d], 1);
        sm->csrc[pos] = (unsigned char)s;
        sm->cdst[pos] = (unsigned char)d;
    }

    // ---- GATv2 layer ----
    for (int i = tid; i < 4 * HID; i += GT) { sm->W[i] = Wl[i]; sm->W[4 * HID + i] = Wr[i]; }
    if (tid < HID) { sm->vec0[tid] = bl[tid]; sm->vec1[tid] = br[tid];
                     sm->vec2[tid] = attv[tid]; sm->vec3[tid] = bv2[tid]; }
    __syncthreads();
    {   // xl -> A, xr -> H  (IN = 4, tiny)
        int k = tid & (HID - 1), vg = tid >> 6;
#pragma unroll 4
        for (int r = 0; r < 16; r++) {
            int v = vg * 16 + r;
            float a = sm->vec0[k], b = sm->vec1[k];
#pragma unroll
            for (int i = 0; i < 4; i++) {
                float xv = sm->xin[v * 4 + i];
                a = fmaf(xv, sm->W[i * HID + k], a);
                b = fmaf(xv, sm->W[4 * HID + i * HID + k], b);
            }
            sm->A[v * HID + k] = a;
            sm->H[v * HID + k] = b;
        }
    }
    __syncthreads();
    // v2 logits fused with exp: half-warp per edge, lrelu(s)*a = 0.6*s*a + 0.4*|s|*a
    {
        int hl = lane & 15;
        float4 at = *(const float4*)&sm->vec2[hl * 4];
#pragma unroll 2
        for (int j = wid * 2 + (lane >> 4); j < EPG; j += NW * 2) {
            int s = sm->csrc[j], d = sm->cdst[j];
            float4 xl = *(const float4*)&sm->A[s * HID + hl * 4];
            float4 xr = *(const float4*)&sm->H[d * HID + hl * 4];
            float s0 = xl.x + xr.x, s1 = xl.y + xr.y, s2 = xl.z + xr.z, s3 = xl.w + xr.w;
            float p = fmaf(s0, at.x, fmaf(s1, at.y, fmaf(s2, at.z, s3 * at.w)));
            float q = fmaf(fabsf(s0), at.x, fmaf(fabsf(s1), at.y,
                      fmaf(fabsf(s2), at.z, fabsf(s3) * at.w)));
            float t = fmaf(0.4f, q, 0.6f * p);
#pragma unroll
            for (int o = 8; o; o >>= 1) t += __shfl_xor_sync(0xffffffffu, t, o);
            if (hl == 0) sm->ae[j] = make_float2(__expf(t), __int_as_float(s * HID));
        }
    }
    __syncthreads();
    // aggregate + bias + lrelu(0.01) + layernorm -> H   (no self-loop in GATv2)
    for (int v = wid; v < NPG; v += NW) {
        int o0 = sm->off[v], o1 = sm->off[v + 1];
        ull acc = 0ull; float ps = 0.f;
#pragma unroll 2
        for (int j = o0; j < o1; j++) {
            float2 t = sm->ae[j];
            ull hv = *(const ull*)&sm->A[__float_as_int(t.y) + lane * 2];
            fma2(acc, pk1(t.x), hv);
            ps += t.x;
        }
        float inv = __fdividef(1.f, ps + 1e-16f);
        float2 r  = unpk(acc);
        float2 b2 = *(const float2*)&sm->vec3[lane * 2];
        float u0 = fmaf(r.x, inv, b2.x);
        float u1 = fmaf(r.y, inv, b2.y);
        float t0 = fmaf(0.495f, fabsf(u0), 0.505f * u0);   // lrelu 0.01
        float t1 = fmaf(0.495f, fabsf(u1), 0.505f * u1);
        float mean = wsum(t0 + t1) * (1.f / 64.f);
        float d0 = t0 - mean, d1 = t1 - mean;
        float var = wsum(d0 * d0 + d1 * d1) * (1.f / 64.f);
        float rstd = rsqrtf(var + 1e-5f);
        float2 gg = *(const float2*)&sm->lng[lane * 2];
        float2 bb = *(const float2*)&sm->lnb[lane * 2];
        float2 o;
        o.x = fmaf(d0 * rstd, gg.x, bb.x);
        o.y = fmaf(d1 * rstd, gg.y, bb.y);
        *(float2*)&sm->H[v * HID + lane * 2] = o;
    }
    __syncthreads();

    // ---- GAT layers 1 & 2 ----
    gat_layer(sm, Wg1, as1, ad1, bg1, tid, wid, lane);
    gat_layer(sm, Wg2, as2, ad2, bg2, tid, wid, lane);

    // ---- write final features ----
    const float4* Hv = (const float4*)sm->H;
    float4* outp = (float4*)(g_h + (size_t)g * NPG * HID);
    for (int i = tid; i < NPG * HID / 4; i += GT) outp[i] = Hv[i];
}

// ---- kernel 2: split-K GEMM  partials[ky] = h[1024,8192(slice)] @ W1, FFMA2 inner ----
__global__ void __launch_bounds__(256) head_gemm(const float* __restrict__ W1)
{
    __shared__ float As[64][16];
    __shared__ float Bs[16][128];
    int m0 = blockIdx.x * 64;
    int ky = blockIdx.y;
    int kbase = ky * (8192 / KSPLIT);
    int tid = threadIdx.x;
    int tx = tid & 15, ty = tid >> 4;
    int r0 = ty * 4, c0 = tx * 8;
    ull acc[4][4];
#pragma unroll
    for (int r = 0; r < 4; r++)
#pragma unroll
        for (int c = 0; c < 4; c++) acc[r][c] = 0ull;

    int ar = tid >> 2, aq = (tid & 3) * 4;
    int brr = tid >> 4, bc = (tid & 15) * 8;
    for (int kk = kbase; kk < kbase + 8192 / KSPLIT; kk += 16) {
        *(float4*)&As[ar][aq]      = *(const float4*)&g_h[(size_t)(m0 + ar) * 8192 + kk + aq];
        *(float4*)&Bs[brr][bc]     = *(const float4*)&W1[(size_t)(kk + brr) * 128 + bc];
        *(float4*)&Bs[brr][bc + 4] = *(const float4*)&W1[(size_t)(kk + brr) * 128 + bc + 4];
        __syncthreads();
#pragma unroll
        for (int k = 0; k < 16; k++) {
            ull a0 = pk1(As[r0][k]),     a1 = pk1(As[r0 + 1][k]);
            ull a2 = pk1(As[r0 + 2][k]), a3 = pk1(As[r0 + 3][k]);
            ull b0 = *(const ull*)&Bs[k][c0];
            ull b1 = *(const ull*)&Bs[k][c0 + 2];
            ull b2 = *(const ull*)&Bs[k][c0 + 4];
            ull b3 = *(const ull*)&Bs[k][c0 + 6];
            fma2(acc[0][0], a0, b0); fma2(acc[0][1], a0, b1); fma2(acc[0][2], a0, b2); fma2(acc[0][3], a0, b3);
            fma2(acc[1][0], a1, b0); fma2(acc[1][1], a1, b1); fma2(acc[1][2], a1, b2); fma2(acc[1][3], a1, b3);
            fma2(acc[2][0], a2, b0); fma2(acc[2][1], a2, b1); fma2(acc[2][2], a2, b2); fma2(acc[2][3], a2, b3);
            fma2(acc[3][0], a3, b0); fma2(acc[3][1], a3, b1); fma2(acc[3][2], a3, b2); fma2(acc[3][3], a3, b3);
        }
        __syncthreads();
    }
    float* outp = g_hp[ky];
#pragma unroll
    for (int r = 0; r < 4; r++)
#pragma unroll
        for (int c = 0; c < 4; c++)
            *(ull*)&outp[(m0 + r0 + r) * 128 + c0 + 2 * c] = acc[r][c];
}

// ---- kernel 3: reduce partials + bias, lrelu, @W2, sigmoid; one warp per graph ----
__global__ void head_final(const float* __restrict__ W2, const float* __restrict__ b2,
                           const float* __restrict__ b1, float* __restrict__ outp)
{
    int g = blockIdx.x * 8 + (threadIdx.x >> 5);
    int lane = threadIdx.x & 31;
    float4 s = make_float4(0.f, 0.f, 0.f, 0.f);
#pragma unroll
    for (int ky = 0; ky < KSPLIT; ky++) {
        float4 p = *(const float4*)&g_hp[ky][(size_t)g * 128 + lane * 4];
        s.x += p.x; s.y += p.y; s.z += p.z; s.w += p.w;
    }
    float4 bb = *(const float4*)&b1[lane * 4];
    s.x += bb.x; s.y += bb.y; s.z += bb.z; s.w += bb.w;
    s.x = fmaf(0.495f, fabsf(s.x), 0.505f * s.x);
    s.y = fmaf(0.495f, fabsf(s.y), 0.505f * s.y);
    s.z = fmaf(0.495f, fabsf(s.z), 0.505f * s.z);
    s.w = fmaf(0.495f, fabsf(s.w), 0.505f * s.w);
    float4 w = *(const float4*)&W2[lane * 4];
    float p = s.x * w.x + s.y * w.y + s.z * w.z + s.w * w.w;
    p = wsum(p);
    if (lane == 0) outp[g] = 1.f / (1.f + expf(-(p + b2[0])));
}

extern "C" void kernel_launch(void* const* d_in, const int* in_sizes, int n_in,
                              void* d_out, int out_size)
{
    const float* x    = (const float*)d_in[0];
    const int*   ei   = (const int*)  d_in[1];
    const float* Wl   = (const float*)d_in[2];
    const float* bl   = (const float*)d_in[3];
    const float* Wr   = (const float*)d_in[4];
    const float* br   = (const float*)d_in[5];
    const float* attv = (const float*)d_in[6];
    const float* bv2  = (const float*)d_in[7];
    const float* Wg1  = (const float*)d_in[8];
    const float* as1  = (const float*)d_in[9];
    const float* ad1  = (const float*)d_in[10];
    const float* bg1  = (const float*)d_in[11];
    const float* Wg2  = (const float*)d_in[12];
    const float* as2  = (const float*)d_in[13];
    const float* ad2  = (const float*)d_in[14];
    const float* bg2  = (const float*)d_in[15];
    const float* lng  = (const float*)d_in[16];
    const float* lnb  = (const float*)d_in[17];
    const float* W1   = (const float*)d_in[18];
    const float* b1   = (const float*)d_in[19];
    const float* W2   = (const float*)d_in[20];
    const float* b2   = (const float*)d_in[21];
    float* outp = (float*)d_out;

    int smem = (int)sizeof(SM);
    cudaFuncSetAttribute(gnn_kernel, cudaFuncAttributeMaxDynamicSharedMemorySize, smem);

    gnn_kernel<<<NGRAPH, GT, smem>>>(x, ei, Wl, bl, Wr, br, attv, bv2,
                                     Wg1, as1, ad1, bg1, Wg2, as2, ad2, bg2, lng, lnb);
    head_gemm<<<dim3(16, KSPLIT), 256>>>(W1);
    head_final<<<NGRAPH / 8, 256>>>(W2, b2, b1, outp);
}